// round 4
// baseline (speedup 1.0000x reference)
#include <cuda_runtime.h>
#include <math.h>

#define BB 64
#define MM 2048
#define CC 64
#define HH 128
#define NNZE 32768
#define H3 384
#define PADN 40960   // per-graph padded edge stream capacity (max 32768+3*2048)

// -------- scratch (static device arrays; no runtime malloc) --------
__device__ int           g_cluscnt[BB*CC];
__device__ int           g_clusoff[BB*CC];
__device__ int           g_cpad[BB*CC];     // padded-stream start per cluster
__device__ unsigned char g_nit[BB*MM];      // per row (cluster order): padded_len/4
__device__ int2          g_csr[BB*PADN];    // cluster-ordered, row-padded edges
__device__ float         g_xdec[BB*CC*H3];
__device__ float         g_Q[BB*CC*HH];
__device__ float         g_K[BB*CC*HH];
__device__ float         g_V[BB*CC*HH];

// ============ K1: build cluster-ordered padded CSR (one CTA / graph) =====
__global__ void __launch_bounds__(1024) k_prep(const int* __restrict__ rows,
                                               const int* __restrict__ cols,
                                               const float* __restrict__ vals,
                                               const int* __restrict__ idx) {
    __shared__ int   hist[MM];        // row edge counts
    __shared__ int   cur[MM];         // per-row padded scatter cursor
    __shared__ int   ss[1024];
    __shared__ short pos2row[MM];     // cluster-ordered row list
    __shared__ int   chist[CC], ccur[CC], coffs[CC];
    int g = blockIdx.x, tid = threadIdx.x;
    hist[tid] = 0; hist[tid + 1024] = 0;
    if (tid < CC) chist[tid] = 0;
    __syncthreads();

    const int* r  = rows + g * NNZE;
    const int* ix = idx  + g * MM;
    for (int i = tid; i < NNZE; i += 1024) atomicAdd(&hist[r[i]], 1);
    int i0 = ix[tid], i1 = ix[tid + 1024];
    atomicAdd(&chist[i0], 1);
    atomicAdd(&chist[i1], 1);
    __syncthreads();

    if (tid == 0) {
        int acc = 0;
        for (int c = 0; c < CC; c++) {
            coffs[c] = acc; ccur[c] = acc;
            g_clusoff[g*CC + c] = acc;
            g_cluscnt[g*CC + c] = chist[c];
            acc += chist[c];
        }
    }
    __syncthreads();

    // order rows by cluster
    int p0 = atomicAdd(&ccur[i0], 1); pos2row[p0] = (short)tid;
    int p1 = atomicAdd(&ccur[i1], 1); pos2row[p1] = (short)(tid + 1024);
    __syncthreads();

    // padded lengths in cluster-order positions; exclusive scan
    int r0 = pos2row[2*tid], r1 = pos2row[2*tid + 1];
    int len0 = hist[r0], len1 = hist[r1];
    int l0 = (len0 + 3) & ~3, l1 = (len1 + 3) & ~3;
    int t = l0 + l1;
    ss[tid] = t;
    __syncthreads();
    for (int off = 1; off < 1024; off <<= 1) {
        int v = (tid >= off) ? ss[tid - off] : 0;
        __syncthreads();
        ss[tid] += v;
        __syncthreads();
    }
    int excl = ss[tid] - t;
    int o0 = excl, o1 = excl + l0;
    cur[r0] = o0;  cur[r1] = o1;
    g_nit[g*MM + 2*tid]     = (unsigned char)(l0 >> 2);
    g_nit[g*MM + 2*tid + 1] = (unsigned char)(l1 >> 2);

    // zero the padding slots
    int2* cbase = g_csr + (size_t)g * PADN;
    for (int k = len0; k < l0; k++) cbase[o0 + k] = make_int2(0, 0);
    for (int k = len1; k < l1; k++) cbase[o1 + k] = make_int2(0, 0);
    __syncthreads();

    // per-cluster padded stream start
    if (tid < CC) {
        int cp = coffs[tid];
        g_cpad[g*CC + tid] = (cp < MM) ? cur[pos2row[cp]] : 0;
    }
    __syncthreads();

    // scatter edges to padded, cluster-ordered positions
    const int*   c = cols + g * NNZE;
    const float* v = vals + g * NNZE;
    for (int i = tid; i < NNZE; i += 1024) {
        int rr = r[i];
        int p = atomicAdd(&cur[rr], 1);
        cbase[p] = make_int2(c[i], __float_as_int(v[i]));
    }
}

// ============ packed f32x2 helpers ============
__device__ __forceinline__ void ffma2(unsigned long long& d,
                                      unsigned long long a,
                                      unsigned long long b) {
    asm("fma.rn.f32x2 %0, %1, %2, %0;" : "+l"(d) : "l"(a), "l"(b));
}
__device__ __forceinline__ unsigned long long pack2(float v) {
    unsigned long long r;
    asm("mov.b64 %0, {%1, %1};" : "=l"(r) : "f"(v));
    return r;
}
__device__ __forceinline__ void unpack2(float& lo, float& hi, unsigned long long v) {
    asm("mov.b64 {%0, %1}, %2;" : "=f"(lo), "=f"(hi) : "l"(v));
}

// ============ K2: SpMM + pooling, streaming padded CSR ============
// CTA = (graph, h-eighth slice of 16 floats). x slice in smem at stride-20
// floats/row (bank-spread). Warp owns 2 clusters; 4 edges per iteration
// (8-lane groups, lane = float2 of the slice). Zero dependent gmem loads in
// the hot loop: csr stream is sequential, row lengths come from smem.
__global__ void __launch_bounds__(1024) k_spmm(const float* __restrict__ x) {
    extern __shared__ char smem_raw[];
    float2* xs = (float2*)smem_raw;                       // 2048 * 10 float2 (163840B)
    int* meta  = (int*)(smem_raw + 2048*10*8);            // coff|ccnt|cpad (768B)
    unsigned char* nit = (unsigned char*)(smem_raw + 2048*10*8 + 768);  // 2048B
    int* coff = meta, *ccnt = meta + 64, *cpad = meta + 128;

    int g = blockIdx.x >> 3, s = blockIdx.x & 7;
    int tid = threadIdx.x;

    // stage x slice: rows at stride 10 float2 (20 floats) to spread banks
    const float4* xg = (const float4*)x + (size_t)g * MM * 32 + s * 4;
    for (int i = tid; i < MM * 4; i += 1024) {
        int row = i >> 2, p = i & 3;
        float4 v = __ldg(&xg[row * 32 + p]);
        int b = row * 10 + p * 2;
        xs[b]     = make_float2(v.x, v.y);
        xs[b + 1] = make_float2(v.z, v.w);
    }
    for (int i = tid; i < MM / 4; i += 1024)
        ((uchar4*)nit)[i] = ((const uchar4*)(g_nit + g * MM))[i];
    if (tid < 64)       coff[tid]       = g_clusoff[g*CC + tid];
    else if (tid < 128) ccnt[tid - 64]  = g_cluscnt[g*CC + tid - 64];
    else if (tid < 192) cpad[tid - 128] = g_cpad[g*CC + tid - 128];
    __syncthreads();

    int wid = tid >> 5, lane = tid & 31;
    int fl = lane & 7;                       // float2 index within slice
    int selhi = (lane >> 3) & 1;             // pick (z,w) vs (x,y) of int4
    const int4* cq = (const int4*)(g_csr + (size_t)g * PADN);

    #pragma unroll
    for (int half = 0; half < 2; half++) {
        int c = wid + half * 32;
        int nr  = ccnt[c];
        int pos = coff[c];
        int eptr = cpad[c];                  // padded edge index (multiple of 4)
        float sx = 0.f, sy = 0.f;
        float mxx = -INFINITY, mxy = -INFINITY;
        for (int j = 0; j < nr; j++) {
            int it = nit[pos + j];
            unsigned long long acc = 0ull;
            const int4* p4 = cq + (eptr >> 1) + (lane >> 4);
            #pragma unroll 2
            for (int tct = 0; tct < it; tct++) {
                int4 q = __ldg(p4); p4 += 2;
                int col   = selhi ? q.z : q.x;
                float val = __int_as_float(selhi ? q.w : q.y);
                unsigned long long xv =
                    *(const unsigned long long*)&xs[col * 10 + fl];
                ffma2(acc, pack2(val), xv);
            }
            eptr += it << 2;
            float ax, ay; unpack2(ax, ay, acc);
            ax += __shfl_xor_sync(0xFFFFFFFFu, ax, 8);
            ay += __shfl_xor_sync(0xFFFFFFFFu, ay, 8);
            ax += __shfl_xor_sync(0xFFFFFFFFu, ax, 16);
            ay += __shfl_xor_sync(0xFFFFFFFFu, ay, 16);
            sx += ax; sy += ay;
            mxx = fmaxf(mxx, ax); mxy = fmaxf(mxy, ay);
        }
        if (lane < 8) {
            float cf = fmaxf((float)nr, 1.f);
            float* xd = g_xdec + (g*CC + c) * H3 + s * 16 + fl * 2;
            xd[0]        = sx / cf;  xd[1]        = sy / cf;
            xd[HH]       = mxx;      xd[HH + 1]   = mxy;
            xd[2*HH]     = sx;       xd[2*HH + 1] = sy;
        }
    }
}

// ============ K3: Q/K/V = x_dec @ W (f32x2 FMA, LDS.128 operand loads) ====
#define XS_LD 68
__global__ void __launch_bounds__(256) k_gemm(const float* __restrict__ Wq,
                                              const float* __restrict__ Wk,
                                              const float* __restrict__ Wv) {
    extern __shared__ float sm[];
    float* xsA = sm;                // [64 k][68 pad] transposed A tile
    float* ws  = sm + 64 * XS_LD;   // [64 k][128 h] W tile
    int g = blockIdx.x, which = blockIdx.y;
    const float* W = (which == 0) ? Wq : (which == 1) ? Wk : Wv;
    float* out = ((which == 0) ? g_Q : (which == 1) ? g_K : g_V) + g * CC * HH;
    const float* xd = g_xdec + g * CC * H3;
    int tid = threadIdx.x;
    int ty = tid >> 4, tx = tid & 15;

    unsigned long long acc[4][4];
    #pragma unroll
    for (int i = 0; i < 4; i++)
        #pragma unroll
        for (int j = 0; j < 4; j++) acc[i][j] = 0ull;

    for (int kt = 0; kt < H3; kt += 64) {
        __syncthreads();
        for (int i = tid; i < 64 * 64; i += 256) {
            int rr = i >> 6, kk = i & 63;
            xsA[kk * XS_LD + rr] = xd[rr * H3 + kt + kk];
        }
        const float4* wsrc = (const float4*)(W + kt * HH);
        for (int i = tid; i < 64 * HH / 4; i += 256) ((float4*)ws)[i] = wsrc[i];
        __syncthreads();
        #pragma unroll 4
        for (int kk = 0; kk < 64; kk++) {
            float4 av = *(const float4*)&xsA[kk * XS_LD + ty * 4];
            ulonglong2 b01 = *(const ulonglong2*)&ws[kk * HH + tx * 8];
            ulonglong2 b23 = *(const ulonglong2*)&ws[kk * HH + tx * 8 + 4];
            unsigned long long pa0 = pack2(av.x), pa1 = pack2(av.y);
            unsigned long long pa2 = pack2(av.z), pa3 = pack2(av.w);
            unsigned long long bv[4] = {b01.x, b01.y, b23.x, b23.y};
            #pragma unroll
            for (int j = 0; j < 4; j++) {
                ffma2(acc[0][j], pa0, bv[j]);
                ffma2(acc[1][j], pa1, bv[j]);
                ffma2(acc[2][j], pa2, bv[j]);
                ffma2(acc[3][j], pa3, bv[j]);
            }
        }
    }
    #pragma unroll
    for (int i = 0; i < 4; i++) {
        unsigned long long* o =
            (unsigned long long*)&out[(ty*4 + i) * HH + tx * 8];
        #pragma unroll
        for (int j = 0; j < 4; j++) o[j] = acc[i][j];
    }
}

// ============ K4: attention, grid (64 graphs x 4 row-quarters) ============
__global__ void __launch_bounds__(256) k_attn(float* __restrict__ out) {
    extern __shared__ float sm[];
    float* Qs = sm;                   // 16 * 132
    float* Ks = Qs + 16 * 132;        // 64 * 132
    float* Vs = Ks + 64 * 132;        // 64 * 132
    float* Ss = Vs + 64 * 132;        // 16 * 68
    int g = blockIdx.x, rh = blockIdx.y * 16, tid = threadIdx.x;
    const float* Qg = g_Q + g * CC * HH + rh * HH;
    const float* Kg = g_K + g * CC * HH;
    const float* Vg = g_V + g * CC * HH;

    for (int i = tid; i < 16 * HH; i += 256) {
        int r = i >> 7, hh = i & 127;
        Qs[r*132 + hh] = Qg[i];
    }
    for (int i = tid; i < CC * HH; i += 256) {
        int r = i >> 7, hh = i & 127;
        Ks[r*132 + hh] = Kg[i];
        Vs[r*132 + hh] = Vg[i];
    }
    __syncthreads();

    int r = tid & 15, grp = tid >> 4;      // 16 rows x 16 col-groups
    {
        float sacc[4] = {0.f, 0.f, 0.f, 0.f};
        const float4* q4 = (const float4*)Qs + r * 33;
        const float4* k4 = (const float4*)Ks;
        #pragma unroll 4
        for (int h4 = 0; h4 < 32; h4++) {
            float4 q = q4[h4];
            #pragma unroll
            for (int cc = 0; cc < 4; cc++) {
                float4 k = k4[(grp*4 + cc) * 33 + h4];
                sacc[cc] += q.x*k.x + q.y*k.y + q.z*k.z + q.w*k.w;
            }
        }
        const float scale = 0.08838834764831845f;   // 1/sqrt(128)
        #pragma unroll
        for (int cc = 0; cc < 4; cc++) Ss[r*68 + grp*4 + cc] = sacc[cc] * scale;
    }
    __syncthreads();
    if (tid < 16) {
        float m = -INFINITY;
        for (int c = 0; c < CC; c++) m = fmaxf(m, Ss[tid*68 + c]);
        float sum = 0.f;
        for (int c = 0; c < CC; c++) {
            float e = __expf(Ss[tid*68 + c] - m);
            Ss[tid*68 + c] = e;
            sum += e;
        }
        float inv = 1.f / sum;
        for (int c = 0; c < CC; c++) Ss[tid*68 + c] *= inv;
    }
    __syncthreads();
    {
        float4 a0 = make_float4(0.f,0.f,0.f,0.f), a1 = a0;
        const float4* v4 = (const float4*)Vs;
        #pragma unroll 4
        for (int c = 0; c < CC; c++) {
            float p = Ss[r*68 + c];
            float4 v0 = v4[c * 33 + grp * 2];
            float4 v1 = v4[c * 33 + grp * 2 + 1];
            a0.x += p*v0.x; a0.y += p*v0.y; a0.z += p*v0.z; a0.w += p*v0.w;
            a1.x += p*v1.x; a1.y += p*v1.y; a1.z += p*v1.z; a1.w += p*v1.w;
        }
        float4* o4 = (float4*)out + g * 2048 + (rh + r) * 32 + grp * 2;
        o4[0] = a0; o4[1] = a1;
    }
}

extern "C" void kernel_launch(void* const* d_in, const int* in_sizes, int n_in,
                              void* d_out, int out_size) {
    const float* x    = (const float*)d_in[0];
    const int*   rows = (const int*)d_in[3];
    const int*   cols = (const int*)d_in[4];
    const float* vals = (const float*)d_in[5];
    const int*   idx  = (const int*)d_in[6];
    const float* Wq   = (const float*)d_in[7];
    const float* Wk   = (const float*)d_in[8];
    const float* Wv   = (const float*)d_in[9];
    float* out = (float*)d_out;

    static const int SPMM_SMEM = 2048*10*8 + 768 + 2048;            // 166656 B
    static const int GEMM_SMEM = (64*XS_LD + 64*HH) * 4;            // 50176 B
    static const int ATTN_SMEM = ((16 + 2*64) * 132 + 16*68) * 4;   // 80384 B
    cudaFuncSetAttribute(k_spmm, cudaFuncAttributeMaxDynamicSharedMemorySize, SPMM_SMEM);
    cudaFuncSetAttribute(k_gemm, cudaFuncAttributeMaxDynamicSharedMemorySize, GEMM_SMEM);
    cudaFuncSetAttribute(k_attn, cudaFuncAttributeMaxDynamicSharedMemorySize, ATTN_SMEM);

    k_prep<<<BB, 1024>>>(rows, cols, vals, idx);
    k_spmm<<<BB * 8, 1024, SPMM_SMEM>>>(x);
    k_gemm<<<dim3(BB, 3), 256, GEMM_SMEM>>>(Wq, Wk, Wv);
    k_attn<<<dim3(BB, 4), 256, ATTN_SMEM>>>(out);
}

// round 5
// speedup vs baseline: 1.9666x; 1.9666x over previous
#include <cuda_runtime.h>
#include <math.h>

#define BB 64
#define MM 2048
#define CC 64
#define HH 128
#define NNZE 32768
#define H3 384
#define PADN 40960   // per-graph padded edge stream capacity (max 32768+3*2048)

// -------- scratch (static device arrays; no runtime malloc) --------
__device__ int           g_cluscnt[BB*CC];
__device__ int           g_clusoff[BB*CC];
__device__ int           g_cpad[BB*CC];     // padded-stream start per cluster
__device__ unsigned char g_nit[BB*MM];      // per row (cluster order): padded_len/4
__device__ int2          g_csr[BB*PADN];    // cluster-ordered, row-padded edges
__device__ float         g_xdec[BB*CC*H3];
__device__ float         g_Q[BB*CC*HH];
__device__ float         g_K[BB*CC*HH];
__device__ float         g_V[BB*CC*HH];

// ============ K1: build cluster-ordered padded CSR (one CTA / graph) =====
__global__ void __launch_bounds__(1024) k_prep(const int* __restrict__ rows,
                                               const int* __restrict__ cols,
                                               const float* __restrict__ vals,
                                               const int* __restrict__ idx) {
    __shared__ int   hist[MM];        // row edge counts
    __shared__ int   cur[MM];         // per-row padded scatter cursor
    __shared__ int   ss[1024];
    __shared__ short pos2row[MM];     // cluster-ordered row list
    __shared__ int   chist[CC], ccur[CC], coffs[CC];
    int g = blockIdx.x, tid = threadIdx.x;
    hist[tid] = 0; hist[tid + 1024] = 0;
    if (tid < CC) chist[tid] = 0;
    __syncthreads();

    const int* r  = rows + g * NNZE;
    const int* ix = idx  + g * MM;
    for (int i = tid; i < NNZE; i += 1024) atomicAdd(&hist[r[i]], 1);
    int i0 = ix[tid], i1 = ix[tid + 1024];
    atomicAdd(&chist[i0], 1);
    atomicAdd(&chist[i1], 1);
    __syncthreads();

    if (tid == 0) {
        int acc = 0;
        for (int c = 0; c < CC; c++) {
            coffs[c] = acc; ccur[c] = acc;
            g_clusoff[g*CC + c] = acc;
            g_cluscnt[g*CC + c] = chist[c];
            acc += chist[c];
        }
    }
    __syncthreads();

    // order rows by cluster
    int p0 = atomicAdd(&ccur[i0], 1); pos2row[p0] = (short)tid;
    int p1 = atomicAdd(&ccur[i1], 1); pos2row[p1] = (short)(tid + 1024);
    __syncthreads();

    // padded lengths in cluster-order positions; exclusive scan
    int r0 = pos2row[2*tid], r1 = pos2row[2*tid + 1];
    int len0 = hist[r0], len1 = hist[r1];
    int l0 = (len0 + 3) & ~3, l1 = (len1 + 3) & ~3;
    int t = l0 + l1;
    ss[tid] = t;
    __syncthreads();
    for (int off = 1; off < 1024; off <<= 1) {
        int v = (tid >= off) ? ss[tid - off] : 0;
        __syncthreads();
        ss[tid] += v;
        __syncthreads();
    }
    int excl = ss[tid] - t;
    int o0 = excl, o1 = excl + l0;
    cur[r0] = o0;  cur[r1] = o1;
    g_nit[g*MM + 2*tid]     = (unsigned char)(l0 >> 2);
    g_nit[g*MM + 2*tid + 1] = (unsigned char)(l1 >> 2);

    // zero the padding slots
    int2* cbase = g_csr + (size_t)g * PADN;
    for (int k = len0; k < l0; k++) cbase[o0 + k] = make_int2(0, 0);
    for (int k = len1; k < l1; k++) cbase[o1 + k] = make_int2(0, 0);
    __syncthreads();

    // per-cluster padded stream start
    if (tid < CC) {
        int cp = coffs[tid];
        g_cpad[g*CC + tid] = (cp < MM) ? cur[pos2row[cp]] : 0;
    }
    __syncthreads();

    // scatter edges to padded, cluster-ordered positions
    const int*   c = cols + g * NNZE;
    const float* v = vals + g * NNZE;
    for (int i = tid; i < NNZE; i += 1024) {
        int rr = r[i];
        int p = atomicAdd(&cur[rr], 1);
        cbase[p] = make_int2(c[i], __float_as_int(v[i]));
    }
}

// ============ K2: SpMM + pooling, MLP-batched L2 gather ============
// Warp = one cluster; lane = one float4 of H=128. Each edge's x gather is
// 4 clean 128B lines; csr stream is sequential (read once per edge) and
// loads are batched 4 edges per iteration (2 int4 + 4 float4, all
// independent). Row lengths broadcast from registers via shfl: no per-row
// memory dependency, no reduction shfls. Pooling stays in registers.
__global__ void __launch_bounds__(256) k_spmm(const float4* __restrict__ x4) {
    int g = blockIdx.x >> 3, q = blockIdx.x & 7;
    int wid = threadIdx.x >> 5, lane = threadIdx.x & 31;
    int c = q * 8 + wid;                       // 8 warps x 8 CTAs = 64 clusters
    int nr   = g_cluscnt[g*CC + c];
    int pos  = g_clusoff[g*CC + c];
    int eptr = g_cpad[g*CC + c];
    const float4* xq = x4 + (size_t)g * MM * 32;
    const int4* cs = (const int4*)(g_csr + (size_t)g * PADN + eptr);
    const unsigned char* nitp = g_nit + g * MM + pos;

    float4 s  = make_float4(0.f, 0.f, 0.f, 0.f);
    float4 mx = make_float4(-INFINITY, -INFINITY, -INFINITY, -INFINITY);

    for (int j0 = 0; j0 < nr; j0 += 32) {
        int lim = min(32, nr - j0);
        int myv = (lane < lim) ? (int)nitp[j0 + lane] : 0;
        for (int j = 0; j < lim; j++) {
            int it = __shfl_sync(0xFFFFFFFFu, myv, j);
            float4 acc = make_float4(0.f, 0.f, 0.f, 0.f);
            #pragma unroll 2
            for (int t = 0; t < it; t++) {
                int4 a = __ldg(cs);
                int4 b = __ldg(cs + 1);
                cs += 2;
                float4 v0 = __ldg(&xq[a.x * 32 + lane]);
                float4 v1 = __ldg(&xq[a.z * 32 + lane]);
                float4 v2 = __ldg(&xq[b.x * 32 + lane]);
                float4 v3 = __ldg(&xq[b.z * 32 + lane]);
                float f0 = __int_as_float(a.y), f1 = __int_as_float(a.w);
                float f2 = __int_as_float(b.y), f3 = __int_as_float(b.w);
                acc.x += f0*v0.x + f1*v1.x + f2*v2.x + f3*v3.x;
                acc.y += f0*v0.y + f1*v1.y + f2*v2.y + f3*v3.y;
                acc.z += f0*v0.z + f1*v1.z + f2*v2.z + f3*v3.z;
                acc.w += f0*v0.w + f1*v1.w + f2*v2.w + f3*v3.w;
            }
            s.x += acc.x; s.y += acc.y; s.z += acc.z; s.w += acc.w;
            mx.x = fmaxf(mx.x, acc.x); mx.y = fmaxf(mx.y, acc.y);
            mx.z = fmaxf(mx.z, acc.z); mx.w = fmaxf(mx.w, acc.w);
        }
    }
    float cf = fmaxf((float)nr, 1.f);
    float* xd = g_xdec + (g*CC + c) * H3;
    float4 mean = make_float4(s.x/cf, s.y/cf, s.z/cf, s.w/cf);
    *(float4*)&xd[lane*4]          = mean;
    *(float4*)&xd[HH + lane*4]     = mx;
    *(float4*)&xd[2*HH + lane*4]   = s;
}

// ============ packed f32x2 helpers ============
__device__ __forceinline__ void ffma2(unsigned long long& d,
                                      unsigned long long a,
                                      unsigned long long b) {
    asm("fma.rn.f32x2 %0, %1, %2, %0;" : "+l"(d) : "l"(a), "l"(b));
}
__device__ __forceinline__ unsigned long long pack2(float v) {
    unsigned long long r;
    asm("mov.b64 %0, {%1, %1};" : "=l"(r) : "f"(v));
    return r;
}

// ============ K3: Q/K/V = x_dec @ W (f32x2 FMA, LDS.128 operand loads) ====
#define XS_LD 68
__global__ void __launch_bounds__(256) k_gemm(const float* __restrict__ Wq,
                                              const float* __restrict__ Wk,
                                              const float* __restrict__ Wv) {
    extern __shared__ float sm[];
    float* xsA = sm;                // [64 k][68 pad] transposed A tile
    float* ws  = sm + 64 * XS_LD;   // [64 k][128 h] W tile
    int g = blockIdx.x, which = blockIdx.y;
    const float* W = (which == 0) ? Wq : (which == 1) ? Wk : Wv;
    float* out = ((which == 0) ? g_Q : (which == 1) ? g_K : g_V) + g * CC * HH;
    const float* xd = g_xdec + g * CC * H3;
    int tid = threadIdx.x;
    int ty = tid >> 4, tx = tid & 15;

    unsigned long long acc[4][4];
    #pragma unroll
    for (int i = 0; i < 4; i++)
        #pragma unroll
        for (int j = 0; j < 4; j++) acc[i][j] = 0ull;

    for (int kt = 0; kt < H3; kt += 64) {
        __syncthreads();
        for (int i = tid; i < 64 * 64; i += 256) {
            int rr = i >> 6, kk = i & 63;
            xsA[kk * XS_LD + rr] = xd[rr * H3 + kt + kk];
        }
        const float4* wsrc = (const float4*)(W + kt * HH);
        for (int i = tid; i < 64 * HH / 4; i += 256) ((float4*)ws)[i] = wsrc[i];
        __syncthreads();
        #pragma unroll 4
        for (int kk = 0; kk < 64; kk++) {
            float4 av = *(const float4*)&xsA[kk * XS_LD + ty * 4];
            ulonglong2 b01 = *(const ulonglong2*)&ws[kk * HH + tx * 8];
            ulonglong2 b23 = *(const ulonglong2*)&ws[kk * HH + tx * 8 + 4];
            unsigned long long pa0 = pack2(av.x), pa1 = pack2(av.y);
            unsigned long long pa2 = pack2(av.z), pa3 = pack2(av.w);
            unsigned long long bv[4] = {b01.x, b01.y, b23.x, b23.y};
            #pragma unroll
            for (int j = 0; j < 4; j++) {
                ffma2(acc[0][j], pa0, bv[j]);
                ffma2(acc[1][j], pa1, bv[j]);
                ffma2(acc[2][j], pa2, bv[j]);
                ffma2(acc[3][j], pa3, bv[j]);
            }
        }
    }
    #pragma unroll
    for (int i = 0; i < 4; i++) {
        unsigned long long* o =
            (unsigned long long*)&out[(ty*4 + i) * HH + tx * 8];
        #pragma unroll
        for (int j = 0; j < 4; j++) o[j] = acc[i][j];
    }
}

// ============ K4: attention, grid (64 graphs x 4 row-quarters) ============
__global__ void __launch_bounds__(256) k_attn(float* __restrict__ out) {
    extern __shared__ float sm[];
    float* Qs = sm;                   // 16 * 132
    float* Ks = Qs + 16 * 132;        // 64 * 132
    float* Vs = Ks + 64 * 132;        // 64 * 132
    float* Ss = Vs + 64 * 132;        // 16 * 68
    int g = blockIdx.x, rh = blockIdx.y * 16, tid = threadIdx.x;
    const float* Qg = g_Q + g * CC * HH + rh * HH;
    const float* Kg = g_K + g * CC * HH;
    const float* Vg = g_V + g * CC * HH;

    for (int i = tid; i < 16 * HH; i += 256) {
        int r = i >> 7, hh = i & 127;
        Qs[r*132 + hh] = Qg[i];
    }
    for (int i = tid; i < CC * HH; i += 256) {
        int r = i >> 7, hh = i & 127;
        Ks[r*132 + hh] = Kg[i];
        Vs[r*132 + hh] = Vg[i];
    }
    __syncthreads();

    int r = tid & 15, grp = tid >> 4;      // 16 rows x 16 col-groups
    {
        float sacc[4] = {0.f, 0.f, 0.f, 0.f};
        const float4* q4 = (const float4*)Qs + r * 33;
        const float4* k4 = (const float4*)Ks;
        #pragma unroll 4
        for (int h4 = 0; h4 < 32; h4++) {
            float4 q = q4[h4];
            #pragma unroll
            for (int cc = 0; cc < 4; cc++) {
                float4 k = k4[(grp*4 + cc) * 33 + h4];
                sacc[cc] += q.x*k.x + q.y*k.y + q.z*k.z + q.w*k.w;
            }
        }
        const float scale = 0.08838834764831845f;   // 1/sqrt(128)
        #pragma unroll
        for (int cc = 0; cc < 4; cc++) Ss[r*68 + grp*4 + cc] = sacc[cc] * scale;
    }
    __syncthreads();
    if (tid < 16) {
        float m = -INFINITY;
        for (int c = 0; c < CC; c++) m = fmaxf(m, Ss[tid*68 + c]);
        float sum = 0.f;
        for (int c = 0; c < CC; c++) {
            float e = __expf(Ss[tid*68 + c] - m);
            Ss[tid*68 + c] = e;
            sum += e;
        }
        float inv = 1.f / sum;
        for (int c = 0; c < CC; c++) Ss[tid*68 + c] *= inv;
    }
    __syncthreads();
    {
        float4 a0 = make_float4(0.f,0.f,0.f,0.f), a1 = a0;
        const float4* v4 = (const float4*)Vs;
        #pragma unroll 4
        for (int c = 0; c < CC; c++) {
            float p = Ss[r*68 + c];
            float4 v0 = v4[c * 33 + grp * 2];
            float4 v1 = v4[c * 33 + grp * 2 + 1];
            a0.x += p*v0.x; a0.y += p*v0.y; a0.z += p*v0.z; a0.w += p*v0.w;
            a1.x += p*v1.x; a1.y += p*v1.y; a1.z += p*v1.z; a1.w += p*v1.w;
        }
        float4* o4 = (float4*)out + g * 2048 + (rh + r) * 32 + grp * 2;
        o4[0] = a0; o4[1] = a1;
    }
}

extern "C" void kernel_launch(void* const* d_in, const int* in_sizes, int n_in,
                              void* d_out, int out_size) {
    const float* x    = (const float*)d_in[0];
    const int*   rows = (const int*)d_in[3];
    const int*   cols = (const int*)d_in[4];
    const float* vals = (const float*)d_in[5];
    const int*   idx  = (const int*)d_in[6];
    const float* Wq   = (const float*)d_in[7];
    const float* Wk   = (const float*)d_in[8];
    const float* Wv   = (const float*)d_in[9];
    float* out = (float*)d_out;

    static const int GEMM_SMEM = (64*XS_LD + 64*HH) * 4;            // 50176 B
    static const int ATTN_SMEM = ((16 + 2*64) * 132 + 16*68) * 4;   // 80384 B
    cudaFuncSetAttribute(k_gemm, cudaFuncAttributeMaxDynamicSharedMemorySize, GEMM_SMEM);
    cudaFuncSetAttribute(k_attn, cudaFuncAttributeMaxDynamicSharedMemorySize, ATTN_SMEM);

    k_prep<<<BB, 1024>>>(rows, cols, vals, idx);
    k_spmm<<<BB * 8, 256>>>((const float4*)x);
    k_gemm<<<dim3(BB, 3), 256, GEMM_SMEM>>>(Wq, Wk, Wv);
    k_attn<<<dim3(BB, 4), 256, ATTN_SMEM>>>(out);
}

// round 6
// speedup vs baseline: 2.1588x; 1.0977x over previous
#include <cuda_runtime.h>
#include <math.h>

#define BB 64
#define MM 2048
#define CC 64
#define HH 128
#define NNZE 32768
#define H3 384
#define PADN 40960   // per-graph padded edge stream capacity (max 32768+3*2048)

// -------- scratch (static device arrays; no runtime malloc) --------
__device__ int           g_cluscnt[BB*CC];
__device__ int           g_clusoff[BB*CC];
__device__ int           g_cpad[BB*CC];     // padded-stream start per cluster
__device__ unsigned char g_nit[BB*MM];      // per row (cluster order): padded_len/4
__device__ int2          g_csr[BB*PADN];    // cluster-ordered, row-padded edges
__device__ float         g_xdec[BB*CC*H3];
__device__ float         g_Q[BB*CC*HH];
__device__ float         g_K[BB*CC*HH];
__device__ float         g_V[BB*CC*HH];

// ============ K1: build cluster-ordered padded CSR (one CTA / graph) =====
__global__ void __launch_bounds__(1024) k_prep(const int* __restrict__ rows,
                                               const int* __restrict__ cols,
                                               const float* __restrict__ vals,
                                               const int* __restrict__ idx) {
    __shared__ int   hist[MM];        // row edge counts
    __shared__ int   cur[MM];         // per-row padded scatter cursor
    __shared__ int   ss[1024];
    __shared__ short pos2row[MM];     // cluster-ordered row list
    __shared__ int   chist[CC], ccur[CC], coffs[CC];
    int g = blockIdx.x, tid = threadIdx.x;
    hist[tid] = 0; hist[tid + 1024] = 0;
    if (tid < CC) chist[tid] = 0;
    __syncthreads();

    const int* r  = rows + g * NNZE;
    const int* ix = idx  + g * MM;
    for (int i = tid; i < NNZE; i += 1024) atomicAdd(&hist[r[i]], 1);
    int i0 = ix[tid], i1 = ix[tid + 1024];
    atomicAdd(&chist[i0], 1);
    atomicAdd(&chist[i1], 1);
    __syncthreads();

    if (tid == 0) {
        int acc = 0;
        for (int c = 0; c < CC; c++) {
            coffs[c] = acc; ccur[c] = acc;
            g_clusoff[g*CC + c] = acc;
            g_cluscnt[g*CC + c] = chist[c];
            acc += chist[c];
        }
    }
    __syncthreads();

    // order rows by cluster
    int p0 = atomicAdd(&ccur[i0], 1); pos2row[p0] = (short)tid;
    int p1 = atomicAdd(&ccur[i1], 1); pos2row[p1] = (short)(tid + 1024);
    __syncthreads();

    // padded lengths in cluster-order positions; exclusive scan
    int r0 = pos2row[2*tid], r1 = pos2row[2*tid + 1];
    int len0 = hist[r0], len1 = hist[r1];
    int l0 = (len0 + 3) & ~3, l1 = (len1 + 3) & ~3;
    int t = l0 + l1;
    ss[tid] = t;
    __syncthreads();
    for (int off = 1; off < 1024; off <<= 1) {
        int v = (tid >= off) ? ss[tid - off] : 0;
        __syncthreads();
        ss[tid] += v;
        __syncthreads();
    }
    int excl = ss[tid] - t;
    int o0 = excl, o1 = excl + l0;
    cur[r0] = o0;  cur[r1] = o1;
    g_nit[g*MM + 2*tid]     = (unsigned char)(l0 >> 2);
    g_nit[g*MM + 2*tid + 1] = (unsigned char)(l1 >> 2);

    // zero the padding slots
    int2* cbase = g_csr + (size_t)g * PADN;
    for (int k = len0; k < l0; k++) cbase[o0 + k] = make_int2(0, 0);
    for (int k = len1; k < l1; k++) cbase[o1 + k] = make_int2(0, 0);
    __syncthreads();

    // per-cluster padded stream start
    if (tid < CC) {
        int cp = coffs[tid];
        g_cpad[g*CC + tid] = (cp < MM) ? cur[pos2row[cp]] : 0;
    }
    __syncthreads();

    // scatter edges to padded, cluster-ordered positions
    const int*   c = cols + g * NNZE;
    const float* v = vals + g * NNZE;
    for (int i = tid; i < NNZE; i += 1024) {
        int rr = r[i];
        int p = atomicAdd(&cur[rr], 1);
        cbase[p] = make_int2(c[i], __float_as_int(v[i]));
    }
}

// ============ K2: SpMM + pooling, MLP-batched L2 gather ============
// 2 warps per cluster (rows split by parity) to double in-flight loads.
// Lane = one float4 of H=128; edges batched 4/iter (2 int4 + 4 float4,
// all independent); row lengths broadcast from registers via shfl. The
// non-owning warp skips a row by advancing its stream pointer. Partials
// combined through smem; pooling stays in registers.
__global__ void __launch_bounds__(256) k_spmm(const float4* __restrict__ x4) {
    __shared__ float comb[4][32][8];
    int g = blockIdx.x >> 4;
    int cgrp = blockIdx.x & 15;
    int wid = threadIdx.x >> 5, lane = threadIdx.x & 31;
    int ci = wid >> 1;                 // cluster within CTA (0..3)
    int sub = wid & 1;                 // row-parity this warp owns
    int c = cgrp * 4 + ci;
    int nr   = g_cluscnt[g*CC + c];
    int pos  = g_clusoff[g*CC + c];
    int eptr = g_cpad[g*CC + c];
    const float4* xq = x4 + (size_t)g * MM * 32;
    const int4* cs = (const int4*)(g_csr + (size_t)g * PADN + eptr);
    const unsigned char* nitp = g_nit + g * MM + pos;

    float4 s  = make_float4(0.f, 0.f, 0.f, 0.f);
    float4 mx = make_float4(-INFINITY, -INFINITY, -INFINITY, -INFINITY);

    for (int j0 = 0; j0 < nr; j0 += 32) {
        int lim = min(32, nr - j0);
        int myv = (lane < lim) ? (int)nitp[j0 + lane] : 0;
        for (int j = 0; j < lim; j++) {
            int it = __shfl_sync(0xFFFFFFFFu, myv, j);
            if (((j0 + j) & 1) == sub) {
                float4 acc = make_float4(0.f, 0.f, 0.f, 0.f);
                #pragma unroll 2
                for (int t = 0; t < it; t++) {
                    int4 a = __ldg(cs);
                    int4 b = __ldg(cs + 1);
                    cs += 2;
                    float4 v0 = __ldg(&xq[a.x * 32 + lane]);
                    float4 v1 = __ldg(&xq[a.z * 32 + lane]);
                    float4 v2 = __ldg(&xq[b.x * 32 + lane]);
                    float4 v3 = __ldg(&xq[b.z * 32 + lane]);
                    float f0 = __int_as_float(a.y), f1 = __int_as_float(a.w);
                    float f2 = __int_as_float(b.y), f3 = __int_as_float(b.w);
                    acc.x += f0*v0.x + f1*v1.x + f2*v2.x + f3*v3.x;
                    acc.y += f0*v0.y + f1*v1.y + f2*v2.y + f3*v3.y;
                    acc.z += f0*v0.z + f1*v1.z + f2*v2.z + f3*v3.z;
                    acc.w += f0*v0.w + f1*v1.w + f2*v2.w + f3*v3.w;
                }
                s.x += acc.x; s.y += acc.y; s.z += acc.z; s.w += acc.w;
                mx.x = fmaxf(mx.x, acc.x); mx.y = fmaxf(mx.y, acc.y);
                mx.z = fmaxf(mx.z, acc.z); mx.w = fmaxf(mx.w, acc.w);
            } else {
                cs += 2 * it;          // skip the other warp's row
            }
        }
    }
    if (sub == 1) {
        float* cb = comb[ci][lane];
        cb[0] = s.x;  cb[1] = s.y;  cb[2] = s.z;  cb[3] = s.w;
        cb[4] = mx.x; cb[5] = mx.y; cb[6] = mx.z; cb[7] = mx.w;
    }
    __syncthreads();
    if (sub == 0) {
        const float* cb = comb[ci][lane];
        s.x += cb[0]; s.y += cb[1]; s.z += cb[2]; s.w += cb[3];
        mx.x = fmaxf(mx.x, cb[4]); mx.y = fmaxf(mx.y, cb[5]);
        mx.z = fmaxf(mx.z, cb[6]); mx.w = fmaxf(mx.w, cb[7]);
        float cf = fmaxf((float)nr, 1.f);
        float* xd = g_xdec + (g*CC + c) * H3;
        float4 mean = make_float4(s.x/cf, s.y/cf, s.z/cf, s.w/cf);
        *(float4*)&xd[lane*4]        = mean;
        *(float4*)&xd[HH + lane*4]   = mx;
        *(float4*)&xd[2*HH + lane*4] = s;
    }
}

// ============ packed f32x2 helpers ============
__device__ __forceinline__ void ffma2(unsigned long long& d,
                                      unsigned long long a,
                                      unsigned long long b) {
    asm("fma.rn.f32x2 %0, %1, %2, %0;" : "+l"(d) : "l"(a), "l"(b));
}
__device__ __forceinline__ unsigned long long pack2(float v) {
    unsigned long long r;
    asm("mov.b64 %0, {%1, %1};" : "=l"(r) : "f"(v));
    return r;
}

// ============ K3: Q/K/V = x_dec @ W, grid (64, 3, 2 N-halves) ============
#define XS_LD 68
__global__ void __launch_bounds__(256) k_gemm(const float* __restrict__ Wq,
                                              const float* __restrict__ Wk,
                                              const float* __restrict__ Wv) {
    extern __shared__ float sm[];
    float* xsA = sm;                // [64 k][68 pad] transposed A tile
    float* ws  = sm + 64 * XS_LD;   // [64 k][64 n-half] W tile
    int g = blockIdx.x, which = blockIdx.y, zh = blockIdx.z;
    const float* W = ((which == 0) ? Wq : (which == 1) ? Wk : Wv) + zh * 64;
    float* out = ((which == 0) ? g_Q : (which == 1) ? g_K : g_V)
                 + g * CC * HH + zh * 64;
    const float* xd = g_xdec + g * CC * H3;
    int tid = threadIdx.x;
    int ty = tid >> 4, tx = tid & 15;

    unsigned long long acc[4][2];
    #pragma unroll
    for (int i = 0; i < 4; i++) { acc[i][0] = 0ull; acc[i][1] = 0ull; }

    for (int kt = 0; kt < H3; kt += 64) {
        __syncthreads();
        for (int i = tid; i < 64 * 64; i += 256) {
            int rr = i >> 6, kk = i & 63;
            xsA[kk * XS_LD + rr] = xd[rr * H3 + kt + kk];
        }
        for (int i = tid; i < 64 * 16; i += 256) {
            int row = i >> 4, cidx = i & 15;
            *(float4*)&ws[row * 64 + cidx * 4] =
                *(const float4*)&W[(kt + row) * HH + cidx * 4];
        }
        __syncthreads();
        #pragma unroll 8
        for (int kk = 0; kk < 64; kk++) {
            float4 av = *(const float4*)&xsA[kk * XS_LD + ty * 4];
            ulonglong2 b = *(const ulonglong2*)&ws[kk * 64 + tx * 4];
            unsigned long long pa0 = pack2(av.x), pa1 = pack2(av.y);
            unsigned long long pa2 = pack2(av.z), pa3 = pack2(av.w);
            ffma2(acc[0][0], pa0, b.x);  ffma2(acc[0][1], pa0, b.y);
            ffma2(acc[1][0], pa1, b.x);  ffma2(acc[1][1], pa1, b.y);
            ffma2(acc[2][0], pa2, b.x);  ffma2(acc[2][1], pa2, b.y);
            ffma2(acc[3][0], pa3, b.x);  ffma2(acc[3][1], pa3, b.y);
        }
    }
    #pragma unroll
    for (int i = 0; i < 4; i++) {
        ulonglong2 o; o.x = acc[i][0]; o.y = acc[i][1];
        *(ulonglong2*)&out[(ty*4 + i) * HH + tx * 4] = o;
    }
}

// ============ K4: attention, grid (64 x 4); V read from gmem (L1) ========
__global__ void __launch_bounds__(256) k_attn(float* __restrict__ out) {
    extern __shared__ float sm[];
    float* Qs = sm;                   // 16 * 132
    float* Ks = Qs + 16 * 132;        // 64 * 132
    float* Ss = Ks + 64 * 132;        // 16 * 68
    int g = blockIdx.x, rh = blockIdx.y * 16, tid = threadIdx.x;
    const float* Qg = g_Q + g * CC * HH + rh * HH;
    const float* Kg = g_K + g * CC * HH;

    for (int i = tid; i < 16 * HH; i += 256) {
        int r = i >> 7, hh = i & 127;
        Qs[r*132 + hh] = Qg[i];
    }
    for (int i = tid; i < CC * HH; i += 256) {
        int r = i >> 7, hh = i & 127;
        Ks[r*132 + hh] = Kg[i];
    }
    __syncthreads();

    int r = tid & 15, grp = tid >> 4;      // 16 rows x 16 col-groups
    {
        float sacc[4] = {0.f, 0.f, 0.f, 0.f};
        const float4* q4 = (const float4*)Qs + r * 33;
        const float4* k4 = (const float4*)Ks;
        #pragma unroll 4
        for (int h4 = 0; h4 < 32; h4++) {
            float4 q = q4[h4];
            #pragma unroll
            for (int cc = 0; cc < 4; cc++) {
                float4 k = k4[(grp*4 + cc) * 33 + h4];
                sacc[cc] += q.x*k.x + q.y*k.y + q.z*k.z + q.w*k.w;
            }
        }
        const float scale = 0.08838834764831845f;   // 1/sqrt(128)
        #pragma unroll
        for (int cc = 0; cc < 4; cc++) Ss[r*68 + grp*4 + cc] = sacc[cc] * scale;
    }
    __syncthreads();
    if (tid < 16) {
        float m = -INFINITY;
        for (int c = 0; c < CC; c++) m = fmaxf(m, Ss[tid*68 + c]);
        float sum = 0.f;
        for (int c = 0; c < CC; c++) {
            float e = __expf(Ss[tid*68 + c] - m);
            Ss[tid*68 + c] = e;
            sum += e;
        }
        float inv = 1.f / sum;
        for (int c = 0; c < CC; c++) Ss[tid*68 + c] *= inv;
    }
    __syncthreads();
    {
        float4 a0 = make_float4(0.f,0.f,0.f,0.f), a1 = a0;
        const float4* v4g = (const float4*)(g_V + g * CC * HH);
        #pragma unroll 4
        for (int c = 0; c < CC; c++) {
            float p = Ss[r*68 + c];
            float4 v0 = __ldg(&v4g[c * 32 + grp * 2]);
            float4 v1 = __ldg(&v4g[c * 32 + grp * 2 + 1]);
            a0.x += p*v0.x; a0.y += p*v0.y; a0.z += p*v0.z; a0.w += p*v0.w;
            a1.x += p*v1.x; a1.y += p*v1.y; a1.z += p*v1.z; a1.w += p*v1.w;
        }
        float4* o4 = (float4*)out + g * 2048 + (rh + r) * 32 + grp * 2;
        o4[0] = a0; o4[1] = a1;
    }
}

extern "C" void kernel_launch(void* const* d_in, const int* in_sizes, int n_in,
                              void* d_out, int out_size) {
    const float* x    = (const float*)d_in[0];
    const int*   rows = (const int*)d_in[3];
    const int*   cols = (const int*)d_in[4];
    const float* vals = (const float*)d_in[5];
    const int*   idx  = (const int*)d_in[6];
    const float* Wq   = (const float*)d_in[7];
    const float* Wk   = (const float*)d_in[8];
    const float* Wv   = (const float*)d_in[9];
    float* out = (float*)d_out;

    static const int GEMM_SMEM = (64*XS_LD + 64*64) * 4;            // 33792 B
    static const int ATTN_SMEM = ((16 + 64) * 132 + 16*68) * 4;     // 46592 B
    cudaFuncSetAttribute(k_gemm, cudaFuncAttributeMaxDynamicSharedMemorySize, GEMM_SMEM);
    cudaFuncSetAttribute(k_attn, cudaFuncAttributeMaxDynamicSharedMemorySize, ATTN_SMEM);

    k_prep<<<BB, 1024>>>(rows, cols, vals, idx);
    k_spmm<<<BB * 16, 256>>>((const float4*)x);
    k_gemm<<<dim3(BB, 3, 2), 256, GEMM_SMEM>>>(Wq, Wk, Wv);
    k_attn<<<dim3(BB, 4), 256, ATTN_SMEM>>>(out);
}

// round 7
// speedup vs baseline: 2.6369x; 1.2215x over previous
#include <cuda_runtime.h>
#include <math.h>

#define BB 64
#define MM 2048
#define CC 64
#define HH 128
#define NNZE 32768
#define H3 384
#define PADN 40960   // per-graph padded edge stream capacity (max 32768+3*2048)

// -------- scratch (static device arrays; no runtime malloc) --------
__device__ int           g_cluscnt[BB*CC];
__device__ int           g_clusoff[BB*CC];
__device__ int           g_csplit[BB*CC*4]; // padded-stream start at row quartiles
__device__ unsigned char g_nit[BB*MM];      // per row (cluster order): padded_len/4
__device__ int2          g_csr[BB*PADN];    // cluster-ordered, row-padded edges
__device__ float         g_xdec[BB*CC*H3];
__device__ float         g_Q[BB*CC*HH];
__device__ float         g_K[BB*CC*HH];
__device__ float         g_V[BB*CC*HH];

// ============ K1: build cluster-ordered padded CSR (one CTA / graph) =====
__global__ void __launch_bounds__(1024) k_prep(const int* __restrict__ rows,
                                               const int* __restrict__ cols,
                                               const float* __restrict__ vals,
                                               const int* __restrict__ idx) {
    __shared__ int   hist[MM];        // row edge counts
    __shared__ int   cur[MM];         // per-row padded scatter cursor
    __shared__ int   ss[1024];
    __shared__ short pos2row[MM];     // cluster-ordered row list
    __shared__ int   chist[CC], ccur[CC], coffs[CC];
    int g = blockIdx.x, tid = threadIdx.x;
    hist[tid] = 0; hist[tid + 1024] = 0;
    if (tid < CC) chist[tid] = 0;
    __syncthreads();

    const int* r  = rows + g * NNZE;
    const int* ix = idx  + g * MM;
    for (int i = tid; i < NNZE; i += 1024) atomicAdd(&hist[r[i]], 1);
    int i0 = ix[tid], i1 = ix[tid + 1024];
    atomicAdd(&chist[i0], 1);
    atomicAdd(&chist[i1], 1);
    __syncthreads();

    if (tid == 0) {
        int acc = 0;
        for (int c = 0; c < CC; c++) {
            coffs[c] = acc; ccur[c] = acc;
            g_clusoff[g*CC + c] = acc;
            g_cluscnt[g*CC + c] = chist[c];
            acc += chist[c];
        }
    }
    __syncthreads();

    // order rows by cluster
    int p0 = atomicAdd(&ccur[i0], 1); pos2row[p0] = (short)tid;
    int p1 = atomicAdd(&ccur[i1], 1); pos2row[p1] = (short)(tid + 1024);
    __syncthreads();

    // padded lengths in cluster-order positions; exclusive scan
    int r0 = pos2row[2*tid], r1 = pos2row[2*tid + 1];
    int len0 = hist[r0], len1 = hist[r1];
    int l0 = (len0 + 3) & ~3, l1 = (len1 + 3) & ~3;
    int t = l0 + l1;
    ss[tid] = t;
    __syncthreads();
    for (int off = 1; off < 1024; off <<= 1) {
        int v = (tid >= off) ? ss[tid - off] : 0;
        __syncthreads();
        ss[tid] += v;
        __syncthreads();
    }
    int excl = ss[tid] - t;
    int o0 = excl, o1 = excl + l0;
    cur[r0] = o0;  cur[r1] = o1;
    g_nit[g*MM + 2*tid]     = (unsigned char)(l0 >> 2);
    g_nit[g*MM + 2*tid + 1] = (unsigned char)(l1 >> 2);

    // zero the padding slots
    int2* cbase = g_csr + (size_t)g * PADN;
    for (int k = len0; k < l0; k++) cbase[o0 + k] = make_int2(0, 0);
    for (int k = len1; k < l1; k++) cbase[o1 + k] = make_int2(0, 0);
    __syncthreads();

    // padded stream start at each cluster's row quartiles
    if (tid < CC) {
        int cp = coffs[tid], nr = chist[tid];
        #pragma unroll
        for (int q = 0; q < 4; q++) {
            int qs = (nr * q) >> 2;
            g_csplit[(g*CC + tid)*4 + q] =
                (nr > 0) ? cur[pos2row[cp + qs]] : 0;
        }
    }
    __syncthreads();

    // scatter edges to padded, cluster-ordered positions
    const int*   c = cols + g * NNZE;
    const float* v = vals + g * NNZE;
    for (int i = tid; i < NNZE; i += 1024) {
        int rr = r[i];
        int p = atomicAdd(&cur[rr], 1);
        cbase[p] = make_int2(c[i], __float_as_int(v[i]));
    }
}

// ============ K2: SpMM + pooling, 4 warps per cluster, contiguous splits ==
// Warp = one row-quartile of one cluster; lane = one float4 of H=128. Each
// warp streams its own contiguous padded edge range (no skip-scanning).
// Edges batched 4/iter (2 int4 + 4 float4 loads, all independent); row
// lengths broadcast from registers via shfl. Partials combined via smem.
__global__ void __launch_bounds__(256) k_spmm(const float4* __restrict__ x4) {
    __shared__ float comb[2][3][32][8];
    int g = blockIdx.x >> 5;                  // 32 CTAs per graph
    int cgrp = blockIdx.x & 31;               // 2 clusters per CTA
    int wid = threadIdx.x >> 5, lane = threadIdx.x & 31;
    int ci = wid >> 2;                        // cluster within CTA (0..1)
    int sub = wid & 3;                        // row-quartile (0..3)
    int c = cgrp * 2 + ci;
    int nr  = g_cluscnt[g*CC + c];
    int pos = g_clusoff[g*CC + c];
    int lo = (nr * sub) >> 2, hi = (nr * (sub + 1)) >> 2;
    int eptr = g_csplit[(g*CC + c)*4 + sub];
    const float4* xq = x4 + (size_t)g * MM * 32;
    const int4* cs = (const int4*)(g_csr + (size_t)g * PADN + eptr);
    const unsigned char* nitp = g_nit + g * MM + pos;

    float4 s  = make_float4(0.f, 0.f, 0.f, 0.f);
    float4 mx = make_float4(-INFINITY, -INFINITY, -INFINITY, -INFINITY);

    for (int j0 = lo; j0 < hi; j0 += 32) {
        int lim = min(32, hi - j0);
        int myv = (lane < lim) ? (int)nitp[j0 + lane] : 0;
        for (int j = 0; j < lim; j++) {
            int it = __shfl_sync(0xFFFFFFFFu, myv, j);
            float4 acc = make_float4(0.f, 0.f, 0.f, 0.f);
            #pragma unroll 2
            for (int t = 0; t < it; t++) {
                int4 a = __ldg(cs);
                int4 b = __ldg(cs + 1);
                cs += 2;
                float4 v0 = __ldg(&xq[a.x * 32 + lane]);
                float4 v1 = __ldg(&xq[a.z * 32 + lane]);
                float4 v2 = __ldg(&xq[b.x * 32 + lane]);
                float4 v3 = __ldg(&xq[b.z * 32 + lane]);
                float f0 = __int_as_float(a.y), f1 = __int_as_float(a.w);
                float f2 = __int_as_float(b.y), f3 = __int_as_float(b.w);
                acc.x += f0*v0.x + f1*v1.x + f2*v2.x + f3*v3.x;
                acc.y += f0*v0.y + f1*v1.y + f2*v2.y + f3*v3.y;
                acc.z += f0*v0.z + f1*v1.z + f2*v2.z + f3*v3.z;
                acc.w += f0*v0.w + f1*v1.w + f2*v2.w + f3*v3.w;
            }
            s.x += acc.x; s.y += acc.y; s.z += acc.z; s.w += acc.w;
            mx.x = fmaxf(mx.x, acc.x); mx.y = fmaxf(mx.y, acc.y);
            mx.z = fmaxf(mx.z, acc.z); mx.w = fmaxf(mx.w, acc.w);
        }
    }
    if (sub != 0) {
        float* cb = comb[ci][sub - 1][lane];
        cb[0] = s.x;  cb[1] = s.y;  cb[2] = s.z;  cb[3] = s.w;
        cb[4] = mx.x; cb[5] = mx.y; cb[6] = mx.z; cb[7] = mx.w;
    }
    __syncthreads();
    if (sub == 0) {
        #pragma unroll
        for (int w = 0; w < 3; w++) {
            const float* cb = comb[ci][w][lane];
            s.x += cb[0]; s.y += cb[1]; s.z += cb[2]; s.w += cb[3];
            mx.x = fmaxf(mx.x, cb[4]); mx.y = fmaxf(mx.y, cb[5]);
            mx.z = fmaxf(mx.z, cb[6]); mx.w = fmaxf(mx.w, cb[7]);
        }
        float cf = fmaxf((float)nr, 1.f);
        float* xd = g_xdec + (g*CC + c) * H3;
        float4 mean = make_float4(s.x/cf, s.y/cf, s.z/cf, s.w/cf);
        *(float4*)&xd[lane*4]        = mean;
        *(float4*)&xd[HH + lane*4]   = mx;
        *(float4*)&xd[2*HH + lane*4] = s;
    }
}

// ============ packed f32x2 helpers ============
__device__ __forceinline__ void ffma2(unsigned long long& d,
                                      unsigned long long a,
                                      unsigned long long b) {
    asm("fma.rn.f32x2 %0, %1, %2, %0;" : "+l"(d) : "l"(a), "l"(b));
}
__device__ __forceinline__ unsigned long long pack2(float v) {
    unsigned long long r;
    asm("mov.b64 %0, {%1, %1};" : "=l"(r) : "f"(v));
    return r;
}

// ============ K3: Q/K/V = x_dec @ W, grid (64, 3, 2 N-halves) ============
#define XS_LD 68
__global__ void __launch_bounds__(256) k_gemm(const float* __restrict__ Wq,
                                              const float* __restrict__ Wk,
                                              const float* __restrict__ Wv) {
    extern __shared__ float sm[];
    float* xsA = sm;                // [64 k][68 pad] transposed A tile
    float* ws  = sm + 64 * XS_LD;   // [64 k][64 n-half] W tile
    int g = blockIdx.x, which = blockIdx.y, zh = blockIdx.z;
    const float* W = ((which == 0) ? Wq : (which == 1) ? Wk : Wv) + zh * 64;
    float* out = ((which == 0) ? g_Q : (which == 1) ? g_K : g_V)
                 + g * CC * HH + zh * 64;
    const float* xd = g_xdec + g * CC * H3;
    int tid = threadIdx.x;
    int ty = tid >> 4, tx = tid & 15;

    unsigned long long acc[4][2];
    #pragma unroll
    for (int i = 0; i < 4; i++) { acc[i][0] = 0ull; acc[i][1] = 0ull; }

    for (int kt = 0; kt < H3; kt += 64) {
        __syncthreads();
        for (int i = tid; i < 64 * 64; i += 256) {
            int rr = i >> 6, kk = i & 63;
            xsA[kk * XS_LD + rr] = xd[rr * H3 + kt + kk];
        }
        for (int i = tid; i < 64 * 16; i += 256) {
            int row = i >> 4, cidx = i & 15;
            *(float4*)&ws[row * 64 + cidx * 4] =
                *(const float4*)&W[(kt + row) * HH + cidx * 4];
        }
        __syncthreads();
        #pragma unroll 8
        for (int kk = 0; kk < 64; kk++) {
            float4 av = *(const float4*)&xsA[kk * XS_LD + ty * 4];
            ulonglong2 b = *(const ulonglong2*)&ws[kk * 64 + tx * 4];
            unsigned long long pa0 = pack2(av.x), pa1 = pack2(av.y);
            unsigned long long pa2 = pack2(av.z), pa3 = pack2(av.w);
            ffma2(acc[0][0], pa0, b.x);  ffma2(acc[0][1], pa0, b.y);
            ffma2(acc[1][0], pa1, b.x);  ffma2(acc[1][1], pa1, b.y);
            ffma2(acc[2][0], pa2, b.x);  ffma2(acc[2][1], pa2, b.y);
            ffma2(acc[3][0], pa3, b.x);  ffma2(acc[3][1], pa3, b.y);
        }
    }
    #pragma unroll
    for (int i = 0; i < 4; i++) {
        ulonglong2 o; o.x = acc[i][0]; o.y = acc[i][1];
        *(ulonglong2*)&out[(ty*4 + i) * HH + tx * 4] = o;
    }
}

// ============ K4: attention, grid (64 x 4), Q/K/V staged in smem ==========
__global__ void __launch_bounds__(256) k_attn(float* __restrict__ out) {
    extern __shared__ float sm[];
    float* Qs = sm;                   // 16 * 132
    float* Ks = Qs + 16 * 132;        // 64 * 132
    float* Vs = Ks + 64 * 132;        // 64 * 132
    float* Ss = Vs + 64 * 132;        // 16 * 68
    int g = blockIdx.x, rh = blockIdx.y * 16, tid = threadIdx.x;
    const float* Qg = g_Q + g * CC * HH + rh * HH;
    const float* Kg = g_K + g * CC * HH;
    const float* Vg = g_V + g * CC * HH;

    for (int i = tid; i < 16 * HH; i += 256) {
        int r = i >> 7, hh = i & 127;
        Qs[r*132 + hh] = Qg[i];
    }
    for (int i = tid; i < CC * HH; i += 256) {
        int r = i >> 7, hh = i & 127;
        Ks[r*132 + hh] = Kg[i];
        Vs[r*132 + hh] = Vg[i];
    }
    __syncthreads();

    int r = tid & 15, grp = tid >> 4;      // 16 rows x 16 col-groups
    {
        float sacc[4] = {0.f, 0.f, 0.f, 0.f};
        const float4* q4 = (const float4*)Qs + r * 33;
        const float4* k4 = (const float4*)Ks;
        #pragma unroll 4
        for (int h4 = 0; h4 < 32; h4++) {
            float4 q = q4[h4];
            #pragma unroll
            for (int cc = 0; cc < 4; cc++) {
                float4 k = k4[(grp*4 + cc) * 33 + h4];
                sacc[cc] += q.x*k.x + q.y*k.y + q.z*k.z + q.w*k.w;
            }
        }
        const float scale = 0.08838834764831845f;   // 1/sqrt(128)
        #pragma unroll
        for (int cc = 0; cc < 4; cc++) Ss[r*68 + grp*4 + cc] = sacc[cc] * scale;
    }
    __syncthreads();
    if (tid < 16) {
        float m = -INFINITY;
        for (int c = 0; c < CC; c++) m = fmaxf(m, Ss[tid*68 + c]);
        float sum = 0.f;
        for (int c = 0; c < CC; c++) {
            float e = __expf(Ss[tid*68 + c] - m);
            Ss[tid*68 + c] = e;
            sum += e;
        }
        float inv = 1.f / sum;
        for (int c = 0; c < CC; c++) Ss[tid*68 + c] *= inv;
    }
    __syncthreads();
    {
        float4 a0 = make_float4(0.f,0.f,0.f,0.f), a1 = a0;
        const float4* v4 = (const float4*)Vs;
        #pragma unroll 4
        for (int c = 0; c < CC; c++) {
            float p = Ss[r*68 + c];
            float4 v0 = v4[c * 33 + grp * 2];
            float4 v1 = v4[c * 33 + grp * 2 + 1];
            a0.x += p*v0.x; a0.y += p*v0.y; a0.z += p*v0.z; a0.w += p*v0.w;
            a1.x += p*v1.x; a1.y += p*v1.y; a1.z += p*v1.z; a1.w += p*v1.w;
        }
        float4* o4 = (float4*)out + g * 2048 + (rh + r) * 32 + grp * 2;
        o4[0] = a0; o4[1] = a1;
    }
}

extern "C" void kernel_launch(void* const* d_in, const int* in_sizes, int n_in,
                              void* d_out, int out_size) {
    const float* x    = (const float*)d_in[0];
    const int*   rows = (const int*)d_in[3];
    const int*   cols = (const int*)d_in[4];
    const float* vals = (const float*)d_in[5];
    const int*   idx  = (const int*)d_in[6];
    const float* Wq   = (const float*)d_in[7];
    const float* Wk   = (const float*)d_in[8];
    const float* Wv   = (const float*)d_in[9];
    float* out = (float*)d_out;

    static const int GEMM_SMEM = (64*XS_LD + 64*64) * 4;            // 33792 B
    static const int ATTN_SMEM = ((16 + 2*64) * 132 + 16*68) * 4;   // 80384 B
    cudaFuncSetAttribute(k_gemm, cudaFuncAttributeMaxDynamicSharedMemorySize, GEMM_SMEM);
    cudaFuncSetAttribute(k_attn, cudaFuncAttributeMaxDynamicSharedMemorySize, ATTN_SMEM);

    k_prep<<<BB, 1024>>>(rows, cols, vals, idx);
    k_spmm<<<BB * 32, 256>>>((const float4*)x);
    k_gemm<<<dim3(BB, 3, 2), 256, GEMM_SMEM>>>(Wq, Wk, Wv);
    k_attn<<<dim3(BB, 4), 256, ATTN_SMEM>>>(out);
}